// round 14
// baseline (speedup 1.0000x reference)
#include <cuda_runtime.h>
#include <cuda_bf16.h>
#include <math.h>

// ---------------------------------------------------------------------------
// Problem constants
// ---------------------------------------------------------------------------
#define N_NODES   10000
#define N_EDGES   250000
#define F_CH      32
#define HIDDEN    64
#define NPATH     11
#define RCOLS     (NPATH * F_CH)   // 352
#define FEAT      288              // 9*F

// Path tables (i, j, k)
__device__ constexpr int PI_(int p) { constexpr int v[NPATH] = {0,0,0,1,1,1,1,2,2,2,2}; return v[p]; }
__device__ constexpr int PJ_(int p) { constexpr int v[NPATH] = {0,1,2,0,1,1,2,0,1,2,2}; return v[p]; }
__device__ constexpr int PK_(int p) { constexpr int v[NPATH] = {0,1,2,1,0,2,1,2,1,0,2}; return v[p]; }
// M-table offsets: sizes (2i+1)(2k+1) = 1,3,5,9,3,15,9,25,15,5,25  (total 115)
__device__ constexpr int MOFF_(int p){ constexpr int v[NPATH+1] = {0,1,4,9,18,21,36,45,70,85,90,115}; return v[p]; }
#define MTOT 115

// W3J tensors, padded [p][a(5)][b(5)][c(5)], PATH_W*0.2 folded in.
__device__ float g_W3J[NPATH * 125];

// ---------------------------------------------------------------------------
// Kernel A: Wigner-3j tensors on device (float fast path; su2_cg in double).
// Mirrors reference _su2_cg -> _q -> _w3j incl. Re/Im-norm selection.
// ---------------------------------------------------------------------------
__device__ __forceinline__ double d_fact(int n) {
    const double f[9] = {1.0, 1.0, 2.0, 6.0, 24.0, 120.0, 720.0, 5040.0, 40320.0};
    return f[n];
}

__device__ double su2_cg(int j1, int j2, int j3, int m1, int m2, int m3) {
    if (m1 + m2 != m3) return 0.0;
    double pref = sqrt((2.0*j3 + 1.0) * d_fact(j1+j2-j3) * d_fact(j1-j2+j3) *
                       d_fact(-j1+j2+j3) / d_fact(j1+j2+j3+1));
    pref *= sqrt(d_fact(j3+m3) * d_fact(j3-m3) * d_fact(j1-m1) *
                 d_fact(j1+m1) * d_fact(j2-m2) * d_fact(j2+m2));
    double s = 0.0;
    for (int k = 0; k <= j1 + j2 - j3; ++k) {
        int d0 = k, d1 = j1+j2-j3-k, d2 = j1-m1-k, d3 = j2+m2-k,
            d4 = j3-j2+m1+k, d5 = j3-j1-m2+k;
        if (d0 < 0 || d1 < 0 || d2 < 0 || d3 < 0 || d4 < 0 || d5 < 0) continue;
        double term = 1.0 / (d_fact(d0)*d_fact(d1)*d_fact(d2)*d_fact(d3)*d_fact(d4)*d_fact(d5));
        s += (k & 1) ? -term : term;
    }
    return pref * s;
}

// q(l)[row][col] including the (-i)^l prefactor (float).
__device__ __forceinline__ void q_entry(int l, int row, int col, float& qr, float& qi) {
    const float is2 = 0.70710678118654752440f;
    int m = row - l;
    float a = 0.0f, b = 0.0f;
    if (m < 0) {
        if (col == l - m) a = is2;        // l + |m|
        if (col == l + m) b = -is2;       // l - |m|
    } else if (m == 0) {
        if (col == l) a = 1.0f;
    } else {
        float sgn = (m & 1) ? -1.0f : 1.0f;
        if (col == l + m) a = sgn * is2;
        if (col == l - m) b = sgn * is2;
    }
    if (l == 1) { float na = b, nb = -a; a = na; b = nb; }   // * (-i)
    else if (l == 2) { a = -a; b = -b; }                      // * (-i)^2
    qr = a; qi = b;
}

__global__ void w3j_init_kernel() {
    int p = blockIdx.x;
    int l1 = PI_(p), l2 = PJ_(p), l3 = PK_(p);
    int n1 = 2*l1 + 1, n2 = 2*l2 + 1, n3 = 2*l3 + 1;
    int tot = n1 * n2 * n3;
    int tid = threadIdx.x;

    __shared__ float sC[125];
    __shared__ float sWr[125], sWi[125];
    __shared__ float snr, sni;

    for (int idx = tid; idx < 125; idx += blockDim.x) g_W3J[p*125 + idx] = 0.0f;

    for (int idx = tid; idx < tot; idx += blockDim.x) {
        int a = idx / (n2*n3), r = idx % (n2*n3), b = r / n3, c = r % n3;
        sC[(a*n2 + b)*n3 + c] = (float)su2_cg(l1, l2, l3, a - l1, b - l2, c - l3);
    }
    if (tid == 0) { snr = 0.0f; sni = 0.0f; }
    __syncthreads();

    for (int idx = tid; idx < tot; idx += blockDim.x) {
        int j  = idx / (n2*n3), r = idx % (n2*n3);
        int lq = r / n3, nn = r % n3;
        float wr = 0.0f, wi = 0.0f;
        for (int a = 0; a < n1; ++a) {
            float q1r, q1i; q_entry(l1, a, j, q1r, q1i);
            for (int b = 0; b < n2; ++b) {
                float q2r, q2i; q_entry(l2, b, lq, q2r, q2i);
                float tr = q1r*q2r - q1i*q2i;
                float ti = q1r*q2i + q1i*q2r;
                for (int c = 0; c < n3; ++c) {
                    float q3r, q3i; q_entry(l3, c, nn, q3r, q3i);
                    float ur = tr*q3r + ti*q3i;     // * conj(q3)
                    float ui = ti*q3r - tr*q3i;
                    float cg = sC[(a*n2 + b)*n3 + c];
                    wr += ur * cg; wi += ui * cg;
                }
            }
        }
        sWr[idx] = wr; sWi[idx] = wi;
        atomicAdd(&snr, wr*wr);
        atomicAdd(&sni, wi*wi);
    }
    __syncthreads();

    bool useR = (snr >= sni);
    float norm = sqrtf(useR ? snr : sni);
    // PATH_W[p] = sqrt((2k+1)/cnt[k]), cnt = {3,4,4}; fold 1/sqrt(25)=0.2
    const float cnt = (l3 == 0) ? 3.0f : 4.0f;
    float scale = sqrtf((2.0f*l3 + 1.0f) / cnt) * 0.2f / norm;

    for (int idx = tid; idx < tot; idx += blockDim.x) {
        int j  = idx / (n2*n3), r = idx % (n2*n3);
        int lq = r / n3, nn = r % n3;
        float v = (useR ? sWr[idx] : sWi[idx]) * scale;
        g_W3J[p*125 + (j*5 + lq)*5 + nn] = v;
    }
}

// ---------------------------------------------------------------------------
// Fused kernel: geometry + bessel + MLP(8->64->352) GEMM + tensor-product
// messages + float4 atomic scatter. 64 edges/block, 256 threads.
//
// Register-layout trick: after the tiled GEMM, warp w / lane u holds
// acc[a][p] = radial[edge 8w+a][32p+u] — exactly the wp[p] layout the
// lane-per-channel contraction consumes. No intermediate global buffer.
//
// Dynamic smem layout (floats):
//   [0,512)       w1
//   [512,576)     b1
//   [576,640)     cut
//   [640,1152)    sph (64 x 8)
//   [1152,2528)   W3J (1376, padded)
//   [2528,3104)   bes (64 x 9)
//   [3104,7264)   h (64 x 65)          } aliased after GEMM by:
//                   row (8 x 288) @3104, M (8 x 120) @5408
//   [7264,12896)  w2 chunk (16 x 352)
// Total 12896 floats = 51584 B (dynamic; attribute set host-side).
// ---------------------------------------------------------------------------
#define SMEM_FLOATS 12896
#define SMEM_BYTES  (SMEM_FLOATS * 4)

__global__ __launch_bounds__(256)
void fused_kernel(const float* __restrict__ nodes,
                  const float* __restrict__ pos,
                  const int*   __restrict__ src,
                  const int*   __restrict__ dst,
                  const float* __restrict__ w1,
                  const float* __restrict__ b1,
                  const float* __restrict__ w2,
                  const float* __restrict__ b2,
                  float*       __restrict__ out)
{
    extern __shared__ float sm[];
    float* sW1  = sm;
    float* sB1  = sm + 512;
    float* sCUT = sm + 576;
    float* sSPH = sm + 640;
    float* sW3  = sm + 1152;
    float* sBES = sm + 2528;
    float* sH   = sm + 3104;
    float* sW2  = sm + 7264;
    float* sROW = sm + 3104;          // alias of sH (post-GEMM)
    float* sM   = sm + 5408;          // alias of sH (post-GEMM)

    const int tid = threadIdx.x;
    const int lane = tid & 31, w = tid >> 5;
    const long ebase = (long)blockIdx.x * 64;

    for (int i = tid; i < 512; i += 256) sW1[i] = w1[i];
    if (tid < 64) sB1[tid] = b1[tid];
    for (int i = tid; i < NPATH*125; i += 256) sW3[i] = g_W3J[i];

    // --- geometry: distance, spherical harmonics, bessel, cutoff (tid<64) ---
    if (tid < 64) {
        long e = ebase + tid;
        float bes[8];
        if (e < N_EDGES) {
            int sn = src[e], dn = dst[e];
            float px = pos[3*sn]   - pos[3*dn];
            float py = pos[3*sn+1] - pos[3*dn+1];
            float pz = pos[3*sn+2] - pos[3*dn+2];
            float d = sqrtf(px*px + py*py + pz*pz);
            float invd = 1.0f / fmaxf(d, 1e-12f);
            float x = px*invd, y = py*invd, z = pz*invd;
            const float s3   = 1.7320508075688772f;
            const float s15  = 3.8729833462074170f;
            const float s5h  = 1.1180339887498949f;   // sqrt(5)/2
            const float s15h = 1.9364916731037085f;   // sqrt(15)/2
            sSPH[tid*8+0] = s3*y;  sSPH[tid*8+1] = s3*z;  sSPH[tid*8+2] = s3*x;
            sSPH[tid*8+3] = s15*x*y; sSPH[tid*8+4] = s15*y*z;
            sSPH[tid*8+5] = s5h*(3.0f*z*z - 1.0f);
            sSPH[tid*8+6] = s15*x*z; sSPH[tid*8+7] = s15h*(x*x - y*y);

            float t  = d * 0.2f;                         // d / BESSEL_END
            float mask = (t > 0.0f && t < 1.0f) ? 1.0f : 0.0f;
            float invt = (t > 0.0f) ? (1.0f / t) : 1.0f;
            const float cb = 0.63245553203367587f;       // sqrt(2/5)
            const float pif = 3.14159265358979323846f;
            #pragma unroll
            for (int n = 0; n < 8; ++n)
                bes[n] = cb * sinf((float)(n+1) * pif * t) * invt * mask;

            float u = d * 0.25f;                         // d / RCUT
            float u2 = u*u, u4 = u2*u2, u5 = u4*u;
            sCUT[tid] = (1.0f - 6.0f*u5 + 5.0f*u5*u) * ((d < 4.0f) ? 1.0f : 0.0f);
        } else {
            #pragma unroll
            for (int n = 0; n < 8; ++n) bes[n] = 0.0f;
            sCUT[tid] = 0.0f;
            #pragma unroll
            for (int q = 0; q < 8; ++q) sSPH[tid*8+q] = 0.0f;
        }
        #pragma unroll
        for (int n = 0; n < 8; ++n) sBES[tid*9+n] = bes[n];
    }
    __syncthreads();

    // --- Phase A: h = silu(bessel @ w1 + b1) ---
    {
        const int e = tid & 63, kg = tid >> 6;
        #pragma unroll
        for (int i2 = 0; i2 < 16; ++i2) {
            int k = kg*16 + i2;
            float acc = sB1[k];
            #pragma unroll
            for (int n = 0; n < 8; ++n) acc += sBES[e*9+n] * sW1[n*64 + k];
            float sig = 1.0f / (1.0f + expf(-acc));
            sH[e*65 + k] = acc * sig;
        }
    }

    // --- Phase B: radial = h @ w2 (register-tiled) ---
    float acc[8][11];
    #pragma unroll
    for (int a = 0; a < 8; ++a)
        #pragma unroll
        for (int j = 0; j < 11; ++j) acc[a][j] = 0.0f;

    for (int k0 = 0; k0 < 64; k0 += 16) {
        __syncthreads();
        const float4* srcv = reinterpret_cast<const float4*>(w2 + k0*352);
        float4* dstv = reinterpret_cast<float4*>(sW2);
        for (int idx = tid; idx < 16*352/4; idx += 256) dstv[idx] = srcv[idx];
        __syncthreads();

        #pragma unroll
        for (int kk = 0; kk < 16; ++kk) {
            float hreg[8];
            #pragma unroll
            for (int a = 0; a < 8; ++a) hreg[a] = sH[(w*8 + a)*65 + k0 + kk];
            float wreg[11];
            #pragma unroll
            for (int j = 0; j < 11; ++j) wreg[j] = sW2[kk*352 + lane + 32*j];
            #pragma unroll
            for (int a = 0; a < 8; ++a)
                #pragma unroll
                for (int j = 0; j < 11; ++j) acc[a][j] += hreg[a] * wreg[j];
        }
    }
    __syncthreads();   // all GEMM reads of sH done before ROW/M aliasing

    // --- Phase C: per-warp tensor-product messages for this warp's 8 edges ---
    float b2r[11];
    #pragma unroll
    for (int p = 0; p < NPATH; ++p) b2r[p] = __ldg(&b2[p*32 + lane]);

    const int u = lane;
    float* rowp = sROW + w*288;
    float* mp   = sM   + w*120;

    for (int a = 0; a < 8; ++a) {
        long e = ebase + w*8 + a;
        if (e >= N_EDGES) break;
        const int le = w*8 + a;
        const int sn = src[e], dn = dst[e];

        // Stage source-node row (coalesced float4)
        const float4* nrow = reinterpret_cast<const float4*>(nodes + (long)sn * FEAT);
        float4* rw = reinterpret_cast<float4*>(rowp);
        rw[lane]      = nrow[lane];
        rw[lane + 32] = nrow[lane + 32];
        if (lane < 8) rw[lane + 64] = nrow[lane + 64];
        __syncwarp();

        float yv[9];
        yv[0] = 1.0f;
        #pragma unroll
        for (int q = 0; q < 8; ++q) yv[1+q] = sSPH[le*8 + q];
        const float cutv = sCUT[le];

        // Per-lane x features (strides 3,5 coprime to 32: conflict-free)
        float xr[9];
        xr[0] = rowp[u];
        #pragma unroll
        for (int q = 0; q < 3; ++q) xr[1+q] = rowp[32 + 3*u + q];
        #pragma unroll
        for (int q = 0; q < 5; ++q) xr[4+q] = rowp[128 + 5*u + q];

        // Radial weights straight from GEMM registers (+b2, *cutoff)
        float wpv[NPATH];
        #pragma unroll
        for (int p = 0; p < NPATH; ++p) wpv[p] = (acc[a][p] + b2r[p]) * cutv;

        // Build M_p[a][c] = sum_b W3J[p][a][b][c] * y_b cooperatively
        #pragma unroll
        for (int rep = 0; rep < 4; ++rep) {
            int ent = lane + rep*32;
            if (ent < MTOT) {
                int p = 0;
                #pragma unroll
                for (int q = 1; q < NPATH; ++q) if (ent >= MOFF_(q)) p = q;
                int rem = ent - MOFF_(p);
                int wk = 2*PK_(p) + 1;
                int aa = rem / wk, cc = rem % wk;
                int j = PJ_(p);
                const float* Wp = &sW3[p*125 + aa*25 + cc];
                float v;
                if (j == 0)      v = Wp[0];
                else if (j == 1) v = Wp[0]*yv[1] + Wp[5]*yv[2] + Wp[10]*yv[3];
                else             v = Wp[0]*yv[4] + Wp[5]*yv[5] + Wp[10]*yv[6]
                                   + Wp[15]*yv[7] + Wp[20]*yv[8];
                mp[ent] = v;
            }
        }
        __syncwarp();

        // Contraction: am += w_p * sum_a x[a] * M_p[a][c]
        float am[9];
        #pragma unroll
        for (int q = 0; q < 9; ++q) am[q] = 0.0f;

        #pragma unroll
        for (int p = 0; p < NPATH; ++p) {
            const int ii = PI_(p), kk = PK_(p);
            const int wk = 2*kk + 1;
            const int mo = MOFF_(p);
            const int xb = (ii == 0) ? 0 : ((ii == 1) ? 1 : 4);
            const int ab = (kk == 0) ? 0 : ((kk == 1) ? 1 : 4);
            #pragma unroll
            for (int c = 0; c < 5; ++c) {
                if (c < wk) {
                    float s = 0.0f;
                    #pragma unroll
                    for (int q = 0; q < 5; ++q) {
                        if (q < 2*ii + 1) s += xr[xb + q] * mp[mo + q*wk + c];
                    }
                    am[ab + c] += wpv[p] * s;
                }
            }
        }

        // Stage message row, flush as 72 coalesced float4 atomics
        __syncwarp();
        rowp[u] = am[0];
        #pragma unroll
        for (int c = 0; c < 3; ++c) rowp[32 + 3*u + c] = am[1+c];
        #pragma unroll
        for (int c = 0; c < 5; ++c) rowp[128 + 5*u + c] = am[4+c];
        __syncwarp();

        float4* ob = reinterpret_cast<float4*>(out) + (long)dn * (FEAT/4);
        const float4* mr = reinterpret_cast<const float4*>(rowp);
        atomicAdd(&ob[lane],      mr[lane]);
        atomicAdd(&ob[lane + 32], mr[lane + 32]);
        if (lane < 8) atomicAdd(&ob[lane + 64], mr[lane + 64]);
        __syncwarp();   // all lanes' LDS for atomics done before next edge's overwrite
    }
}

// ---------------------------------------------------------------------------
// Entry point
// ---------------------------------------------------------------------------
extern "C" void kernel_launch(void* const* d_in, const int* in_sizes, int n_in,
                              void* d_out, int out_size)
{
    const float* nodes = (const float*)d_in[0];
    const float* pos   = (const float*)d_in[1];
    const int*   src   = (const int*)  d_in[2];
    const int*   dst   = (const int*)  d_in[3];
    const float* w1    = (const float*)d_in[4];
    const float* b1    = (const float*)d_in[5];
    const float* w2    = (const float*)d_in[6];
    const float* b2    = (const float*)d_in[7];
    float* out = (float*)d_out;

    cudaFuncSetAttribute(fused_kernel,
                         cudaFuncAttributeMaxDynamicSharedMemorySize, SMEM_BYTES);

    w3j_init_kernel<<<NPATH, 128>>>();
    cudaMemsetAsync(out, 0, (size_t)out_size * sizeof(float));
    fused_kernel<<<(N_EDGES + 63) / 64, 256, SMEM_BYTES>>>(
        nodes, pos, src, dst, w1, b1, w2, b2, out);
}